// round 5
// baseline (speedup 1.0000x reference)
#include <cuda_runtime.h>
#include <cstdint>

// out = sum_{b, k != labels[b]} exp( -||inputs[b,:] - decoded[b,k,:]||^2 )
// B=4096, K=64, DIM=512, fp32. Pure HBM stream over decoded (512 MiB).
//
// Grid = 8192 CTAs x 64 threads, regs forced <= 32 via launch_bounds(64,32)
// -> 32 CTAs/SM resident (2048 threads, block-cap occupancy). Each CTA does
// half a batch row (2 warps x 16 k-rows). 6-shuffle dual-row reduction.

#define B_    4096
#define K_    64
#define DIM_  512

__global__ void init_kernel(float* out) {
    if (threadIdx.x == 0) out[0] = 0.0f;
}

__global__ __launch_bounds__(64, 32)
void mse_exp_loss_kernel(const float* __restrict__ inputs,
                         const float* __restrict__ decoded,
                         const long long* __restrict__ labels,
                         float* __restrict__ out) {
    const int b    = blockIdx.x >> 1;           // 2 CTAs per batch row
    const int half = blockIdx.x & 1;
    const int warp = threadIdx.x >> 5;          // 0..1
    const int lane = threadIdx.x & 31;
    const int k0   = half * 32 + warp * 16;     // this warp's 16 k-rows
    const int lbl  = (int)__ldg(&labels[b]);

    // stage inputs[b] in registers: 16 floats/lane, reused for 16 rows
    const float4* inrow = reinterpret_cast<const float4*>(
        inputs + (size_t)b * DIM_);
    float4 x[4];
    #pragma unroll
    for (int i = 0; i < 4; i++) x[i] = __ldg(&inrow[lane + i * 32]);

    const float4* dbase = reinterpret_cast<const float4*>(
        decoded + ((size_t)b * K_ + k0) * DIM_);

    float acc = 0.0f;

    #pragma unroll
    for (int kk = 0; kk < 16; kk += 2) {
        const float4* r0 = dbase + (kk    ) * (DIM_ / 4);
        const float4* r1 = dbase + (kk + 1) * (DIM_ / 4);

        float4 d0[4], d1[4];
        #pragma unroll
        for (int i = 0; i < 4; i++) d0[i] = __ldcs(&r0[lane + i * 32]);
        #pragma unroll
        for (int i = 0; i < 4; i++) d1[i] = __ldcs(&r1[lane + i * 32]);

        float s0 = 0.0f, s1 = 0.0f;
        #pragma unroll
        for (int i = 0; i < 4; i++) {
            float e;
            e = x[i].x - d0[i].x; s0 = fmaf(e, e, s0);
            e = x[i].y - d0[i].y; s0 = fmaf(e, e, s0);
            e = x[i].z - d0[i].z; s0 = fmaf(e, e, s0);
            e = x[i].w - d0[i].w; s0 = fmaf(e, e, s0);
            e = x[i].x - d1[i].x; s1 = fmaf(e, e, s1);
            e = x[i].y - d1[i].y; s1 = fmaf(e, e, s1);
            e = x[i].z - d1[i].z; s1 = fmaf(e, e, s1);
            e = x[i].w - d1[i].w; s1 = fmaf(e, e, s1);
        }

        // dual reduction in 6 shuffles: fold across the xor-16 boundary so
        // lanes 0-15 carry s0 pair-partials and lanes 16-31 carry s1's, then
        // 4 shared butterfly steps. Lane 0 ends with sum(s0), lane 16 sum(s1).
        const float t0 = __shfl_xor_sync(0xFFFFFFFFu, s0, 16);
        const float t1 = __shfl_xor_sync(0xFFFFFFFFu, s1, 16);
        float v = (lane < 16) ? (s0 + t0) : (s1 + t1);
        #pragma unroll
        for (int o = 8; o > 0; o >>= 1)
            v += __shfl_xor_sync(0xFFFFFFFFu, v, o);

        if (lane == 0 && (k0 + kk     != lbl)) acc += __expf(-v);
        if (lane == 16 && (k0 + kk + 1 != lbl)) acc += __expf(-v);
    }

    // fold lane16's accumulator into lane0
    acc += __shfl_xor_sync(0xFFFFFFFFu, acc, 16);

    // exp(-s) with s ~ 1024 underflows to +0; skipping a +0 add is exact and
    // avoids 16384 same-address L2 atomics bunching at the end.
    if (lane == 0 && acc != 0.0f)
        atomicAdd(out, acc);
}

extern "C" void kernel_launch(void* const* d_in, const int* in_sizes, int n_in,
                              void* d_out, int out_size) {
    const float*     inputs  = (const float*)d_in[0];
    const float*     decoded = (const float*)d_in[1];
    const long long* labels  = (const long long*)d_in[2];
    float* out = (float*)d_out;

    init_kernel<<<1, 32>>>(out);
    mse_exp_loss_kernel<<<B_ * 2, 64>>>(inputs, decoded, labels, out);
}

// round 6
// speedup vs baseline: 1.1775x; 1.1775x over previous
#include <cuda_runtime.h>
#include <cstdint>

// out = sum_{b, k != labels[b]} exp( -||inputs[b,:] - decoded[b,k,:]||^2 )
// B=4096, K=64, DIM=512, fp32. Pure HBM stream over decoded (512 MiB).
//
// Grid = 16384 CTAs x 64 threads: quarter batch-row per CTA (2 warps x
// 8 k-rows). Rotating 2-row software prefetch keeps 8 LDG.128 in flight
// through the FMA/SHFL/exp phase (duty ~100%). Registers left free
// (~90) — R5 proved that capping regs (occupancy) loses to load depth.

#define B_    4096
#define K_    64
#define DIM_  512

__global__ void init_kernel(float* out) {
    if (threadIdx.x == 0) out[0] = 0.0f;
}

__global__ __launch_bounds__(64)
void mse_exp_loss_kernel(const float* __restrict__ inputs,
                         const float* __restrict__ decoded,
                         const long long* __restrict__ labels,
                         float* __restrict__ out) {
    const int b    = blockIdx.x >> 2;           // 4 CTAs per batch row
    const int quad = blockIdx.x & 3;
    const int warp = threadIdx.x >> 5;          // 0..1
    const int lane = threadIdx.x & 31;
    const int k0   = quad * 16 + warp * 8;      // this warp's 8 k-rows

    const float4* dbase = reinterpret_cast<const float4*>(
        decoded + ((size_t)b * K_ + k0) * DIM_);

    // issue first row-pair's streaming loads before anything else
    float4 d0[4], d1[4];
    #pragma unroll
    for (int i = 0; i < 4; i++) d0[i] = __ldcs(&dbase[             lane + i * 32]);
    #pragma unroll
    for (int i = 0; i < 4; i++) d1[i] = __ldcs(&dbase[(DIM_ / 4) + lane + i * 32]);

    const int lbl = (int)__ldg(&labels[b]);

    // stage inputs[b] in registers (16 floats/lane, reused for 8 rows;
    // served from L2 — inputs is only 8 MiB, stays resident)
    const float4* inrow = reinterpret_cast<const float4*>(
        inputs + (size_t)b * DIM_);
    float4 x[4];
    #pragma unroll
    for (int i = 0; i < 4; i++) x[i] = __ldg(&inrow[lane + i * 32]);

    float acc = 0.0f;

    #pragma unroll
    for (int kk = 0; kk < 8; kk += 2) {
        // prefetch next row pair while current pair is consumed below
        float4 n0[4], n1[4];
        if (kk + 2 < 8) {
            const float4* p0 = dbase + (kk + 2) * (DIM_ / 4);
            const float4* p1 = dbase + (kk + 3) * (DIM_ / 4);
            #pragma unroll
            for (int i = 0; i < 4; i++) n0[i] = __ldcs(&p0[lane + i * 32]);
            #pragma unroll
            for (int i = 0; i < 4; i++) n1[i] = __ldcs(&p1[lane + i * 32]);
        }

        float s0 = 0.0f, s1 = 0.0f;
        #pragma unroll
        for (int i = 0; i < 4; i++) {
            float e;
            e = x[i].x - d0[i].x; s0 = fmaf(e, e, s0);
            e = x[i].y - d0[i].y; s0 = fmaf(e, e, s0);
            e = x[i].z - d0[i].z; s0 = fmaf(e, e, s0);
            e = x[i].w - d0[i].w; s0 = fmaf(e, e, s0);
            e = x[i].x - d1[i].x; s1 = fmaf(e, e, s1);
            e = x[i].y - d1[i].y; s1 = fmaf(e, e, s1);
            e = x[i].z - d1[i].z; s1 = fmaf(e, e, s1);
            e = x[i].w - d1[i].w; s1 = fmaf(e, e, s1);
        }

        // dual reduction in 6 shuffles: fold across the xor-16 boundary so
        // lanes 0-15 carry s0 pair-partials, lanes 16-31 carry s1's, then
        // 4 shared butterfly steps. Lane 0 holds sum(s0), lane 16 sum(s1).
        const float t0 = __shfl_xor_sync(0xFFFFFFFFu, s0, 16);
        const float t1 = __shfl_xor_sync(0xFFFFFFFFu, s1, 16);
        float v = (lane < 16) ? (s0 + t0) : (s1 + t1);
        #pragma unroll
        for (int o = 8; o > 0; o >>= 1)
            v += __shfl_xor_sync(0xFFFFFFFFu, v, o);

        if (lane == 0  && (k0 + kk     != lbl)) acc += __expf(-v);
        if (lane == 16 && (k0 + kk + 1 != lbl)) acc += __expf(-v);

        // rotate buffers (fully unrolled -> pure register rename)
        if (kk + 2 < 8) {
            #pragma unroll
            for (int i = 0; i < 4; i++) { d0[i] = n0[i]; d1[i] = n1[i]; }
        }
    }

    // fold lane16's accumulator into lane0
    acc += __shfl_xor_sync(0xFFFFFFFFu, acc, 16);

    // exp(-s) with s ~ 1024 underflows to +0; skipping a +0 add is exact and
    // avoids 32768 same-address L2 atomics bunching at the end.
    if (lane == 0 && acc != 0.0f)
        atomicAdd(out, acc);
}

extern "C" void kernel_launch(void* const* d_in, const int* in_sizes, int n_in,
                              void* d_out, int out_size) {
    const float*     inputs  = (const float*)d_in[0];
    const float*     decoded = (const float*)d_in[1];
    const long long* labels  = (const long long*)d_in[2];
    float* out = (float*)d_out;

    init_kernel<<<1, 32>>>(out);
    mse_exp_loss_kernel<<<B_ * 4, 64>>>(inputs, decoded, labels, out);
}